// round 2
// baseline (speedup 1.0000x reference)
#include <cuda_runtime.h>

// SparseBiasDiagUnfolder: gather off-diagonal 8x8 window entries.
// adj: (B=2, N=2048, N=2048, F=16) f32
// out: (B=2, S=511, 56*16=896) f32
// out[b, s, k*16+f] = adj[b, 4*s + ii(k), 4*s + jj(k), f]
// where local = k + 1 + k/8 (skips diagonal multiples of 9), ii = local/8, jj = local%8.
//
// Latency-bound gather: unroll U=4 per thread with front-batched independent
// LDG.128s (MLP_p1=4) and stride-blockDim element mapping so STG.128s stay
// perfectly coalesced across the warp.

namespace {
constexpr int B  = 2;
constexpr int N  = 2048;
constexpr int S  = 511;            // window starts (0..2040 step 4)
constexpr int K  = 56;             // off-diagonal pairs per window
constexpr int TOT4 = B * S * K * 4; // float4 outputs = 228864
constexpr int U  = 4;              // unroll per thread
constexpr int TPB = 256;
constexpr int BLOCKS = (TOT4 + TPB * U - 1) / (TPB * U); // 224
}

__device__ __forceinline__ int src_index(int t) {
    int f4   = t & 3;            // float4 within 16-float feature vec
    int t2   = t >> 2;           // (b, s, k)
    int k    = t2 % K;
    int rest = t2 / K;
    int s    = rest % S;
    int b    = rest / S;

    int local = k + 1 + (k >> 3);    // skip diagonal
    int r = (s << 2) + (local >> 3);
    int c = (s << 2) + (local & 7);
    return (((b * N) + r) * N + c) * 4 + f4;
}

__global__ void __launch_bounds__(TPB)
sparse_diag_unfold_kernel(const float4* __restrict__ adj4,
                          float4* __restrict__ out4) {
    int base = blockIdx.x * (TPB * U) + threadIdx.x;

    float4 v[U];
    // Front-batched independent loads: maximize memory-level parallelism.
    #pragma unroll
    for (int u = 0; u < U; u++) {
        int t = base + u * TPB;
        if (t < TOT4) {
            v[u] = __ldg(&adj4[src_index(t)]);
        }
    }
    // Coalesced stores (consecutive lanes -> consecutive float4s).
    #pragma unroll
    for (int u = 0; u < U; u++) {
        int t = base + u * TPB;
        if (t < TOT4) {
            out4[t] = v[u];
        }
    }
}

extern "C" void kernel_launch(void* const* d_in, const int* in_sizes, int n_in,
                              void* d_out, int out_size) {
    const float4* adj4 = (const float4*)d_in[0];
    float4* out4 = (float4*)d_out;
    sparse_diag_unfold_kernel<<<BLOCKS, TPB>>>(adj4, out4);
}

// round 5
// speedup vs baseline: 1.0048x; 1.0048x over previous
#include <cuda_runtime.h>

// SparseBiasDiagUnfolder: gather off-diagonal 8x8 window entries.
// adj: (B=2, N=2048, N=2048, F=16) f32
// out: (B=2, S=511, 56*16=896) f32
// out[b, s, k*16+f] = adj[b, 4*s + ii(k), 4*s + jj(k), f]
// local = k + 1 + k/8 (skips diagonal multiples of 9), ii = local/8, jj = local%8.
//
// TOT4 = 2*511*56*4 = 228928 = 2^6 * 7^2 * 73 float4 outputs.
// Exact tiling: TPB=224 (7 warps), U=2 -> 511 blocks, zero predication.
// All 511 tiny CTAs resident in one wave (~3.4 CTAs/SM, ~24 warps/SM) ->
// enough independent LDG.128s in flight to cover DRAM latency.

namespace {
constexpr int B  = 2;
constexpr int N  = 2048;
constexpr int S  = 511;
constexpr int K  = 56;
constexpr int TOT4 = B * S * K * 4;      // 228928
constexpr int U  = 2;
constexpr int TPB = 224;
constexpr int BLOCKS = TOT4 / (TPB * U); // 511
static_assert(BLOCKS * TPB * U == TOT4, "exact tiling");
}

__device__ __forceinline__ int src_index(int t) {
    int f4   = t & 3;            // float4 within the 16-float feature vec
    int t2   = t >> 2;           // (b, s, k)
    int k    = t2 % K;
    int rest = t2 / K;
    int s    = rest % S;
    int b    = rest / S;

    int local = k + 1 + (k >> 3);    // skip diagonal
    int r = (s << 2) + (local >> 3);
    int c = (s << 2) + (local & 7);
    return (((b * N) + r) * N + c) * 4 + f4;
}

__global__ void __launch_bounds__(TPB)
sparse_diag_unfold_kernel(const float4* __restrict__ adj4,
                          float4* __restrict__ out4) {
    int base = blockIdx.x * (TPB * U) + threadIdx.x;

    // Front-batched independent loads (no predication -> max MLP).
    float4 v0 = __ldg(&adj4[src_index(base)]);
    float4 v1 = __ldg(&adj4[src_index(base + TPB)]);

    // Fully coalesced stores.
    out4[base]       = v0;
    out4[base + TPB] = v1;
}

extern "C" void kernel_launch(void* const* d_in, const int* in_sizes, int n_in,
                              void* d_out, int out_size) {
    const float4* adj4 = (const float4*)d_in[0];
    float4* out4 = (float4*)d_out;
    sparse_diag_unfold_kernel<<<BLOCKS, TPB>>>(adj4, out4);
}

// round 6
// speedup vs baseline: 1.0505x; 1.0455x over previous
#include <cuda_runtime.h>

// SparseBiasDiagUnfolder: gather off-diagonal 8x8 window entries.
// adj: (B=2, N=2048, N=2048, F=16) f32
// out: (B=2, S=511, 56*16=896) f32
// out[b, s, k*16+f] = adj[b, 4*s + ii(k), 4*s + jj(k), f]
// local = k + 1 + k/8 (skips diagonal multiples of 9), ii = local/8, jj = local%8.
//
// TOT4 = 2*511*56*4 = 228928 = 2^6 * 7^2 * 73 float4 outputs.
// Exact tiling: TPB=64, U=7 -> 511 blocks, zero predication.
// Each thread front-batches 7 independent LDG.128s (max per-warp MLP;
// ~7.4 MB in flight chip-wide, >= the whole L2-resident read band),
// stride-TPB mapping keeps STG.128s perfectly coalesced.

namespace {
constexpr int B  = 2;
constexpr int N  = 2048;
constexpr int S  = 511;
constexpr int K  = 56;
constexpr int TOT4 = B * S * K * 4;      // 228928
constexpr int U  = 7;
constexpr int TPB = 64;
constexpr int BLOCKS = TOT4 / (TPB * U); // 511
static_assert(BLOCKS * TPB * U == TOT4, "exact tiling");
}

__device__ __forceinline__ int src_index(int t) {
    int f4   = t & 3;            // float4 within the 16-float feature vec
    int t2   = t >> 2;           // (b, s, k)
    int k    = t2 % K;
    int rest = t2 / K;
    int s    = rest % S;
    int b    = rest / S;

    int local = k + 1 + (k >> 3);    // skip diagonal
    int r = (s << 2) + (local >> 3);
    int c = (s << 2) + (local & 7);
    return (((b * N) + r) * N + c) * 4 + f4;
}

__global__ void __launch_bounds__(TPB)
sparse_diag_unfold_kernel(const float4* __restrict__ adj4,
                          float4* __restrict__ out4) {
    const int base = blockIdx.x * (TPB * U) + threadIdx.x;

    // Front-batched independent loads — ptxas keeps these as 7 back-to-back
    // LDG.128s (no guards, no dependencies between them).
    float4 v[U];
    #pragma unroll
    for (int u = 0; u < U; u++) {
        v[u] = __ldg(&adj4[src_index(base + u * TPB)]);
    }

    // Fully coalesced stores.
    #pragma unroll
    for (int u = 0; u < U; u++) {
        out4[base + u * TPB] = v[u];
    }
}

extern "C" void kernel_launch(void* const* d_in, const int* in_sizes, int n_in,
                              void* d_out, int out_size) {
    const float4* adj4 = (const float4*)d_in[0];
    float4* out4 = (float4*)d_out;
    sparse_diag_unfold_kernel<<<BLOCKS, TPB>>>(adj4, out4);
}